// round 12
// baseline (speedup 1.0000x reference)
#include <cuda_runtime.h>
#include <cuda_fp16.h>
#include <math_constants.h>
#include <cstdint>

// Problem constants
#define S_LEN   2048
#define DMODEL  2048
#define NHEADS  16
#define HDIM    128
#define BATCH   4
#define MROWS   (BATCH * S_LEN)   // 8192

// ---------------------------------------------------------------------------
// Scratch (device globals; no allocation in kernel_launch)
// ---------------------------------------------------------------------------
__device__ __half g_xh[(size_t)MROWS * DMODEL];                // x, fp16
__device__ __half g_wh[4][(size_t)DMODEL * DMODEL];            // weights, fp16
__device__ __half g_qhi[(size_t)BATCH * NHEADS * S_LEN * HDIM];
__device__ __half g_qlo[(size_t)BATCH * NHEADS * S_LEN * HDIM];
__device__ __half g_khi[(size_t)BATCH * NHEADS * S_LEN * HDIM];
__device__ __half g_vhi[(size_t)BATCH * NHEADS * S_LEN * HDIM];
__device__ __half g_atth[(size_t)MROWS * DMODEL];              // [B,S,D]
__device__ float g_ct[64 * S_LEN];                              // cos[d][s]
__device__ float g_st[64 * S_LEN];                              // sin[d][s]

// ---------------------------------------------------------------------------
// PTX helpers
// ---------------------------------------------------------------------------
__device__ __forceinline__ void cp16(uint32_t smem_dst, const void* gptr) {
    asm volatile("cp.async.cg.shared.global [%0], [%1], 16;"
                 :: "r"(smem_dst), "l"(__cvta_generic_to_global(gptr)) : "memory");
}
__device__ __forceinline__ void cp_commit() {
    asm volatile("cp.async.commit_group;" ::: "memory");
}
template <int N>
__device__ __forceinline__ void cp_wait() {
    asm volatile("cp.async.wait_group %0;" :: "n"(N) : "memory");
}
__device__ __forceinline__ void ldsm4(uint32_t addr, uint32_t r[4]) {
    asm volatile("ldmatrix.sync.aligned.m8n8.x4.shared.b16 {%0,%1,%2,%3}, [%4];"
                 : "=r"(r[0]), "=r"(r[1]), "=r"(r[2]), "=r"(r[3]) : "r"(addr));
}
__device__ __forceinline__ void ldsm4t(uint32_t addr, uint32_t r[4]) {
    asm volatile("ldmatrix.sync.aligned.m8n8.x4.trans.shared.b16 {%0,%1,%2,%3}, [%4];"
                 : "=r"(r[0]), "=r"(r[1]), "=r"(r[2]), "=r"(r[3]) : "r"(addr));
}
__device__ __forceinline__ void mma16816(float c[4], const uint32_t a[4],
                                         const uint32_t b0, const uint32_t b1) {
    asm volatile(
        "mma.sync.aligned.m16n8k16.row.col.f32.f16.f16.f32 "
        "{%0,%1,%2,%3}, {%4,%5,%6,%7}, {%8,%9}, {%0,%1,%2,%3};"
        : "+f"(c[0]), "+f"(c[1]), "+f"(c[2]), "+f"(c[3])
        : "r"(a[0]), "r"(a[1]), "r"(a[2]), "r"(a[3]), "r"(b0), "r"(b1));
}
__device__ __forceinline__ uint32_t pack_h2(float x, float y) {
    __half2 t = __floats2half2_rn(x, y);
    return *reinterpret_cast<uint32_t*>(&t);
}

// ---------------------------------------------------------------------------
// Fused fp32 -> fp16 converts: y = 0 -> x, y = 1..4 -> Wq/Wk/Wv/Wo
// ---------------------------------------------------------------------------
__global__ void convert_all_kernel(const float4* __restrict__ x,
                                   const float4* __restrict__ w0,
                                   const float4* __restrict__ w1,
                                   const float4* __restrict__ w2,
                                   const float4* __restrict__ w3,
                                   int n4x, int n4w)
{
    const int which = blockIdx.y;
    const float4* src;
    __half* dst;
    int n4;
    if (which == 0)      { src = x;  dst = g_xh;    n4 = n4x; }
    else if (which == 1) { src = w0; dst = g_wh[0]; n4 = n4w; }
    else if (which == 2) { src = w1; dst = g_wh[1]; n4 = n4w; }
    else if (which == 3) { src = w2; dst = g_wh[2]; n4 = n4w; }
    else                 { src = w3; dst = g_wh[3]; n4 = n4w; }

    for (int i = blockIdx.x * blockDim.x + threadIdx.x; i < n4;
         i += gridDim.x * blockDim.x) {
        float4 v = src[i];
        __half2* hp = reinterpret_cast<__half2*>(dst + 4 * (size_t)i);
        hp[0] = __floats2half2_rn(v.x, v.y);
        hp[1] = __floats2half2_rn(v.z, v.w);
    }
}

// ---------------------------------------------------------------------------
// RoPE cos/sin tables: g_ct[d*2048+s], d in [0,64)
// ---------------------------------------------------------------------------
__global__ void rope_tab_kernel()
{
    int i = blockIdx.x * blockDim.x + threadIdx.x;
    if (i >= 64 * S_LEN) return;
    int d = i >> 11, s = i & 2047;
    float invf = (float)exp2(-(double)d * 0.20762050593045952);  // log2(1e4)/64
    float th = (float)s * invf;
    float c, sn;
    sincosf(th, &sn, &c);
    g_ct[i] = c;
    g_st[i] = sn;
}

// ---------------------------------------------------------------------------
// HMMA GEMM (fp16, single-product): tile 64x256, BK=64, 8 warps (2m x 4n),
// warp 32x64, 2 CTAs/SM.  RoPE fused into the Q/K epilogues via smem staging.
// mode: 0=Q(->g_qhi/g_qlo) 1=K(->g_khi) 2=V(->g_vhi) 3=Wo(A=g_atth,->out)
// QKV launch: mode_in = -1 => mode = blockIdx.z.
// smem/stage: A 8K | B 32K = 40KB, 2 stages = 80KB (epilogue reuses as
// a 64 x 264-float fp32 staging tile = 67.6KB)
// ---------------------------------------------------------------------------
#define GM_BM 64
#define GM_BN 256
#define GM_BK 64
#define GM_NIT (DMODEL / GM_BK)          // 32
#define GM_A 0
#define GM_B 8192
#define GM_STAGE 40960
#define GM_SMEM (2 * GM_STAGE)           // 80KB
#define EP_STRIDE 264                    // fp32 stage stride (floats)

__device__ __forceinline__ void gm_load_stage(
    uint32_t t0, int kt, int m0, int n0, int tid,
    const __half* __restrict__ Ah, const __half* __restrict__ Bh)
{
    const int k0 = kt * GM_BK;
    #pragma unroll
    for (int i = 0; i < 2; i++) {
        int lin = tid + i * 256;
        int row = lin >> 3, ch = lin & 7;
        uint32_t soff = (uint32_t)(row * 128 + ((ch ^ (row & 7)) << 4));
        size_t ga = (size_t)(m0 + row) * DMODEL + k0 + ch * 8;
        cp16(t0 + GM_A + soff, Ah + ga);
    }
    #pragma unroll
    for (int i = 0; i < 8; i++) {
        int lin = tid + i * 256;
        int row = lin >> 3, ch = lin & 7;
        uint32_t soff = (uint32_t)(row * 128 + ((ch ^ (row & 7)) << 4));
        size_t gb = (size_t)(n0 + row) * DMODEL + k0 + ch * 8;
        cp16(t0 + GM_B + soff, Bh + gb);
    }
}

__global__ __launch_bounds__(256, 2)
void gemm_hmma(float* __restrict__ Dout, int mode_in)
{
    extern __shared__ char smraw[];
    const uint32_t sbase = (uint32_t)__cvta_generic_to_shared(smraw);
    const int tid  = threadIdx.x;
    const int warp = tid >> 5;
    const int lane = tid & 31;
    const int m0 = blockIdx.y * GM_BM;
    const int n0 = blockIdx.x * GM_BN;
    const int mode = (mode_in < 0) ? (int)blockIdx.z : mode_in;

    const __half* Ah = (mode == 3) ? g_atth : g_xh;
    const __half* Bh = g_wh[mode];

    const int wm = warp & 1;        // 0..1
    const int wn = warp >> 1;       // 0..3
    const int quad = lane >> 3;
    const int lr   = lane & 7;

    int arow[2];
    #pragma unroll
    for (int i = 0; i < 2; i++) arow[i] = wm * 32 + i * 16 + (quad & 1) * 8 + lr;
    const int aqp = quad >> 1;
    int brow[4];
    #pragma unroll
    for (int j = 0; j < 4; j++) brow[j] = wn * 64 + j * 16 + (quad >> 1) * 8 + lr;
    const int bqp = quad & 1;

    float c[2][8][4];
    #pragma unroll
    for (int i = 0; i < 2; i++)
        #pragma unroll
        for (int j = 0; j < 8; j++)
            #pragma unroll
            for (int e = 0; e < 4; e++) c[i][j][e] = 0.f;

    gm_load_stage(sbase, 0, m0, n0, tid, Ah, Bh);
    cp_commit();

    #pragma unroll 1
    for (int kt = 0; kt < GM_NIT; kt++) {
        if (kt + 1 < GM_NIT) {
            gm_load_stage(sbase + ((kt + 1) & 1) * GM_STAGE, kt + 1,
                          m0, n0, tid, Ah, Bh);
            cp_commit();
            cp_wait<1>();
        } else {
            cp_wait<0>();
        }
        __syncthreads();

        const uint32_t t0 = sbase + (kt & 1) * GM_STAGE;
        #pragma unroll
        for (int s = 0; s < 4; s++) {
            uint32_t ah[2][4];
            #pragma unroll
            for (int i = 0; i < 2; i++) {
                uint32_t off = (uint32_t)(arow[i] * 128 +
                               (((s * 2 + aqp) ^ (arow[i] & 7)) << 4));
                ldsm4(t0 + GM_A + off, ah[i]);
            }
            uint32_t bh[8][2];
            #pragma unroll
            for (int j2 = 0; j2 < 4; j2++) {
                uint32_t off = (uint32_t)(brow[j2] * 128 +
                               (((s * 2 + bqp) ^ (brow[j2] & 7)) << 4));
                uint32_t t[4];
                ldsm4(t0 + GM_B + off, t);
                bh[2*j2][0] = t[0]; bh[2*j2][1] = t[1];
                bh[2*j2+1][0] = t[2]; bh[2*j2+1][1] = t[3];
            }
            #pragma unroll
            for (int i = 0; i < 2; i++)
                #pragma unroll
                for (int j = 0; j < 8; j++)
                    mma16816(c[i][j], ah[i], bh[j][0], bh[j][1]);
        }
        __syncthreads();
    }

    // ---------------- epilogue ----------------
    if (mode <= 1) {
        // RoPE fused: stage fp32 C tile in smem, gather (d, d+64) pairs.
        float* cs = reinterpret_cast<float*>(smraw);
        #pragma unroll
        for (int i = 0; i < 2; i++) {
            int rl0 = wm * 32 + i * 16 + (lane >> 2);
            #pragma unroll
            for (int half = 0; half < 2; half++) {
                int rl = rl0 + half * 8;
                #pragma unroll
                for (int j = 0; j < 8; j++) {
                    int cl = wn * 64 + j * 8 + (lane & 3) * 2;
                    cs[rl * EP_STRIDE + cl]     = c[i][j][half * 2];
                    cs[rl * EP_STRIDE + cl + 1] = c[i][j][half * 2 + 1];
                }
            }
        }
        __syncthreads();

        __half* dhi = (mode == 0) ? g_qhi : g_khi;
        #pragma unroll
        for (int it = 0; it < 32; it++) {
            int p = tid + it * 256;            // 8192 pairs
            int rl = p >> 7;                   // 0..63
            int rest = p & 127;
            int hblk = rest >> 6, d = rest & 63;
            float lo = cs[rl * EP_STRIDE + hblk * 128 + d];
            float hi = cs[rl * EP_STRIDE + hblk * 128 + d + 64];
            int r = m0 + rl;
            int bb = r >> 11, ss = r & 2047;
            float cc = g_ct[d * S_LEN + ss];
            float sn = g_st[d * S_LEN + ss];
            float v0 = lo * cc - hi * sn;
            float v1 = hi * cc + lo * sn;
            int h = (n0 >> 7) + hblk;
            size_t base = (((size_t)bb * NHEADS + h) * S_LEN + ss) * HDIM;
            __half h0 = __float2half(v0);
            __half h1 = __float2half(v1);
            dhi[base + d]      = h0;
            dhi[base + d + 64] = h1;
            if (mode == 0) {
                g_qlo[base + d]      = __float2half(v0 - __half2float(h0));
                g_qlo[base + d + 64] = __float2half(v1 - __half2float(h1));
            }
        }
    } else {
        #pragma unroll
        for (int i = 0; i < 2; i++) {
            int r0 = m0 + wm * 32 + i * 16 + (lane >> 2);
            #pragma unroll
            for (int half = 0; half < 2; half++) {
                int r = r0 + half * 8;
                int bb = r >> 11, ss = r & 2047;
                #pragma unroll
                for (int j = 0; j < 8; j++) {
                    int col = n0 + wn * 64 + j * 8 + (lane & 3) * 2;
                    float2 v2 = make_float2(c[i][j][half * 2], c[i][j][half * 2 + 1]);
                    if (mode == 2) {
                        int h = col >> 7, d = col & 127;
                        size_t base = (((size_t)bb * NHEADS + h) * S_LEN + ss) * HDIM + d;
                        *(__half2*)(g_vhi + base) = __floats2half2_rn(v2.x, v2.y);
                    } else {
                        *(float2*)(Dout + (size_t)r * DMODEL + col) = v2;
                    }
                }
            }
        }
    }
}

// ---------------------------------------------------------------------------
// HMMA flash attention (causal, fp16): CTA = 64 q rows x 64-key tiles,
// 4 warps (128 thr), warp = 16 q rows x all 64 keys, 2 CTAs/SM.
// QK: Q hi+lo (2 products). PV: P hi only.
// smem: Qhi 16K | Qlo 16K | 2 stages x (Khi 16K | Vhi 16K) = 96KB
// ---------------------------------------------------------------------------
#define FA_BM 64
#define FQHI 0
#define FQLO 16384
#define FSTG(s) (32768 + (s) * 32768)
#define FKHI 0
#define FVHI 16384
#define FA_SMEM (32768 + 2 * 32768)   // 96KB

__device__ __forceinline__ uint32_t fswz(int row, int ch) {
    return (uint32_t)(row * 256 + ((ch >> 3) << 7) + (((ch & 7) ^ (row & 7)) << 4));
}

__global__ __launch_bounds__(128, 2)
void flash_hmma()
{
    extern __shared__ char smraw[];
    const uint32_t sb = (uint32_t)__cvta_generic_to_shared(smraw);
    const int tid  = threadIdx.x;
    const int w    = tid >> 5;           // 0..3
    const int lane = tid & 31;
    const int quad = lane >> 3;
    const int lr   = lane & 7;
    const int qt = 31 - blockIdx.x;      // heavy CTAs first, 64-row tiles
    const int bh = blockIdx.y;

    const __half* qhib = g_qhi + (size_t)bh * S_LEN * HDIM;
    const __half* qlob = g_qlo + (size_t)bh * S_LEN * HDIM;
    const __half* khib = g_khi + (size_t)bh * S_LEN * HDIM;
    const __half* vhib = g_vhi + (size_t)bh * S_LEN * HDIM;

    #pragma unroll
    for (int i = 0; i < 8; i++) {
        int lin = tid + i * 128;
        int row = lin >> 4, ch = lin & 15;
        uint32_t so = fswz(row, ch);
        size_t go = (size_t)(qt * FA_BM + row) * HDIM + ch * 8;
        cp16(sb + FQHI + so, qhib + go);
        cp16(sb + FQLO + so, qlob + go);
    }
    cp_commit();

    const int nkt = qt + 1;

    {
        const uint32_t t0 = sb + FSTG(0);
        #pragma unroll
        for (int i = 0; i < 8; i++) {
            int lin = tid + i * 128;
            int row = lin >> 4, ch = lin & 15;
            uint32_t so = fswz(row, ch);
            size_t go = (size_t)row * HDIM + ch * 8;
            cp16(t0 + FKHI + so, khib + go);
            cp16(t0 + FVHI + so, vhib + go);
        }
        cp_commit();
    }

    float o[16][4];
    #pragma unroll
    for (int i = 0; i < 16; i++)
        #pragma unroll
        for (int e = 0; e < 4; e++) o[i][e] = 0.f;
    float mi[2] = {-CUDART_INF_F, -CUDART_INF_F};
    float li[2] = {0.f, 0.f};

    const float scale = 0.08838834764831845f;
    const int ar  = 16 * w + (quad & 1) * 8 + lr;
    const int aqp = quad >> 1;
    const int krb = (quad >> 1) * 8 + lr;
    const int bqp = quad & 1;
    const int vrb = (quad & 1) * 8 + lr;
    const int vqp = quad >> 1;

    #pragma unroll 1
    for (int kt = 0; kt < nkt; kt++) {
        if (kt + 1 < nkt) {
            const uint32_t t0 = sb + FSTG((kt + 1) & 1);
            #pragma unroll
            for (int i = 0; i < 8; i++) {
                int lin = tid + i * 128;
                int row = lin >> 4, ch = lin & 15;
                uint32_t so = fswz(row, ch);
                size_t go = (size_t)((kt + 1) * 64 + row) * HDIM + ch * 8;
                cp16(t0 + FKHI + so, khib + go);
                cp16(t0 + FVHI + so, vhib + go);
            }
            cp_commit();
            cp_wait<1>();
        } else {
            cp_wait<0>();
        }
        __syncthreads();

        const uint32_t stg = sb + FSTG(kt & 1);

        float sc[8][4];
        #pragma unroll
        for (int i = 0; i < 8; i++)
            #pragma unroll
            for (int e = 0; e < 4; e++) sc[i][e] = 0.f;

        #pragma unroll
        for (int s = 0; s < 8; s++) {
            uint32_t qh[4], ql[4];
            uint32_t ao = fswz(ar, s * 2 + aqp);
            ldsm4(sb + FQHI + ao, qh);
            ldsm4(sb + FQLO + ao, ql);
            #pragma unroll
            for (int j2 = 0; j2 < 4; j2++) {
                uint32_t bo = fswz(j2 * 16 + krb, s * 2 + bqp);
                uint32_t th[4];
                ldsm4(stg + FKHI + bo, th);
                mma16816(sc[2*j2],   qh, th[0], th[1]);
                mma16816(sc[2*j2],   ql, th[0], th[1]);
                mma16816(sc[2*j2+1], qh, th[2], th[3]);
                mma16816(sc[2*j2+1], ql, th[2], th[3]);
            }
        }

        const bool needmask = (kt * 64 + 63 > qt * FA_BM + 16 * w);
        const int rbase = qt * FA_BM + 16 * w + (lane >> 2);
        #pragma unroll
        for (int half = 0; half < 2; half++) {
            const int rg = rbase + half * 8;
            float mx = -CUDART_INF_F;
            #pragma unroll
            for (int dj = 0; dj < 8; dj++) {
                #pragma unroll
                for (int e = 0; e < 2; e++) {
                    float v = sc[dj][half * 2 + e] * scale;
                    if (needmask) {
                        int col = kt * 64 + dj * 8 + (lane & 3) * 2 + e;
                        if (col > rg) v = -CUDART_INF_F;
                    }
                    sc[dj][half * 2 + e] = v;
                    mx = fmaxf(mx, v);
                }
            }
            mx = fmaxf(mx, __shfl_xor_sync(0xffffffffu, mx, 1));
            mx = fmaxf(mx, __shfl_xor_sync(0xffffffffu, mx, 2));
            float mnew = fmaxf(mi[half], mx);
            float fct  = __expf(mi[half] - mnew);
            mi[half] = mnew;
            float ssum = 0.f;
            #pragma unroll
            for (int dj = 0; dj < 8; dj++) {
                #pragma unroll
                for (int e = 0; e < 2; e++) {
                    float p = __expf(sc[dj][half * 2 + e] - mnew);
                    sc[dj][half * 2 + e] = p;
                    ssum += p;
                }
            }
            ssum += __shfl_xor_sync(0xffffffffu, ssum, 1);
            ssum += __shfl_xor_sync(0xffffffffu, ssum, 2);
            li[half] = li[half] * fct + ssum;
            #pragma unroll
            for (int dt = 0; dt < 16; dt++) {
                o[dt][half * 2]     *= fct;
                o[dt][half * 2 + 1] *= fct;
            }
        }

        #pragma unroll
        for (int t = 0; t < 4; t++) {
            uint32_t ph[4];
            #pragma unroll
            for (int pair = 0; pair < 2; pair++) {
                const float* sp = sc[2 * t + pair];
                ph[pair * 2 + 0] = pack_h2(sp[0], sp[1]);
                ph[pair * 2 + 1] = pack_h2(sp[2], sp[3]);
            }
            #pragma unroll
            for (int j2 = 0; j2 < 8; j2++) {
                uint32_t vo = fswz(t * 16 + vrb, j2 * 2 + vqp);
                uint32_t vh[4];
                ldsm4t(stg + FVHI + vo, vh);
                mma16816(o[2*j2],   ph, vh[0], vh[1]);
                mma16816(o[2*j2+1], ph, vh[2], vh[3]);
            }
        }
        __syncthreads();
    }

    const int b  = bh >> 4;
    const int hh = bh & 15;
    const float inva = 1.0f / li[0];
    const float invb = 1.0f / li[1];
    const int sa = qt * FA_BM + 16 * w + (lane >> 2);

    #pragma unroll
    for (int dj = 0; dj < 16; dj++) {
        int col = hh * HDIM + dj * 8 + (lane & 3) * 2;
        size_t ia = ((size_t)b * S_LEN + sa) * DMODEL + col;
        size_t ib = ((size_t)b * S_LEN + sa + 8) * DMODEL + col;
        *(__half2*)(g_atth + ia) = __floats2half2_rn(o[dj][0] * inva, o[dj][1] * inva);
        *(__half2*)(g_atth + ib) = __floats2half2_rn(o[dj][2] * invb, o[dj][3] * invb);
    }
}

// ---------------------------------------------------------------------------
// Launch
// ---------------------------------------------------------------------------
extern "C" void kernel_launch(void* const* d_in, const int* in_sizes, int n_in,
                              void* d_out, int out_size)
{
    const float* x  = (const float*)d_in[0];
    const float* Wq = (const float*)d_in[1];
    const float* Wk = (const float*)d_in[2];
    const float* Wv = (const float*)d_in[3];
    const float* Wo = (const float*)d_in[4];
    float* out = (float*)d_out;

    int n4x = MROWS * DMODEL / 4;
    int n4w = DMODEL * DMODEL / 4;
    convert_all_kernel<<<dim3(1024, 5), 256>>>(
        (const float4*)x, (const float4*)Wq, (const float4*)Wk,
        (const float4*)Wv, (const float4*)Wo, n4x, n4w);
    rope_tab_kernel<<<(64 * S_LEN + 255) / 256, 256>>>();

    cudaFuncSetAttribute(gemm_hmma,
                         cudaFuncAttributeMaxDynamicSharedMemorySize, GM_SMEM);

    dim3 gblk(DMODEL / GM_BN, MROWS / GM_BM);       // 8 x 128

    // fused Q/K/V projections (single-product, RoPE fused): blockIdx.z = mode
    gemm_hmma<<<dim3(gblk.x, gblk.y, 3), 256, GM_SMEM>>>(nullptr, -1);

    cudaFuncSetAttribute(flash_hmma, cudaFuncAttributeMaxDynamicSharedMemorySize, FA_SMEM);
    flash_hmma<<<dim3(32, BATCH * NHEADS), 128, FA_SMEM>>>();

    gemm_hmma<<<gblk, 256, GM_SMEM>>>(out, 3);   // output projection (1-product)
}

// round 13
// speedup vs baseline: 1.0556x; 1.0556x over previous
#include <cuda_runtime.h>
#include <cuda_fp16.h>
#include <math_constants.h>
#include <cstdint>

// Problem constants
#define S_LEN   2048
#define DMODEL  2048
#define NHEADS  16
#define HDIM    128
#define BATCH   4
#define MROWS   (BATCH * S_LEN)   // 8192

// ---------------------------------------------------------------------------
// Scratch (device globals; no allocation in kernel_launch)
// ---------------------------------------------------------------------------
__device__ __half g_xh[(size_t)MROWS * DMODEL];                // x, fp16
__device__ __half g_wh[4][(size_t)DMODEL * DMODEL];            // weights, fp16
__device__ __half g_qhi[(size_t)BATCH * NHEADS * S_LEN * HDIM];
__device__ __half g_qlo[(size_t)BATCH * NHEADS * S_LEN * HDIM];
__device__ __half g_khi[(size_t)BATCH * NHEADS * S_LEN * HDIM];
__device__ __half g_vhi[(size_t)BATCH * NHEADS * S_LEN * HDIM];
__device__ __half g_atth[(size_t)MROWS * DMODEL];              // [B,S,D]
__device__ float g_ct[64 * S_LEN];                              // cos[d][s]
__device__ float g_st[64 * S_LEN];                              // sin[d][s]

// ---------------------------------------------------------------------------
// PTX helpers
// ---------------------------------------------------------------------------
__device__ __forceinline__ void cp16(uint32_t smem_dst, const void* gptr) {
    asm volatile("cp.async.cg.shared.global [%0], [%1], 16;"
                 :: "r"(smem_dst), "l"(__cvta_generic_to_global(gptr)) : "memory");
}
__device__ __forceinline__ void cp_commit() {
    asm volatile("cp.async.commit_group;" ::: "memory");
}
template <int N>
__device__ __forceinline__ void cp_wait() {
    asm volatile("cp.async.wait_group %0;" :: "n"(N) : "memory");
}
__device__ __forceinline__ void ldsm4(uint32_t addr, uint32_t r[4]) {
    asm volatile("ldmatrix.sync.aligned.m8n8.x4.shared.b16 {%0,%1,%2,%3}, [%4];"
                 : "=r"(r[0]), "=r"(r[1]), "=r"(r[2]), "=r"(r[3]) : "r"(addr));
}
__device__ __forceinline__ void ldsm4t(uint32_t addr, uint32_t r[4]) {
    asm volatile("ldmatrix.sync.aligned.m8n8.x4.trans.shared.b16 {%0,%1,%2,%3}, [%4];"
                 : "=r"(r[0]), "=r"(r[1]), "=r"(r[2]), "=r"(r[3]) : "r"(addr));
}
__device__ __forceinline__ void mma16816(float c[4], const uint32_t a[4],
                                         const uint32_t b0, const uint32_t b1) {
    asm volatile(
        "mma.sync.aligned.m16n8k16.row.col.f32.f16.f16.f32 "
        "{%0,%1,%2,%3}, {%4,%5,%6,%7}, {%8,%9}, {%0,%1,%2,%3};"
        : "+f"(c[0]), "+f"(c[1]), "+f"(c[2]), "+f"(c[3])
        : "r"(a[0]), "r"(a[1]), "r"(a[2]), "r"(a[3]), "r"(b0), "r"(b1));
}
__device__ __forceinline__ uint32_t pack_h2(float x, float y) {
    __half2 t = __floats2half2_rn(x, y);
    return *reinterpret_cast<uint32_t*>(&t);
}

// ---------------------------------------------------------------------------
// Fused fp32 -> fp16 converts: y = 0 -> x, y = 1..4 -> Wq/Wk/Wv/Wo
// ---------------------------------------------------------------------------
__global__ void convert_all_kernel(const float4* __restrict__ x,
                                   const float4* __restrict__ w0,
                                   const float4* __restrict__ w1,
                                   const float4* __restrict__ w2,
                                   const float4* __restrict__ w3,
                                   int n4x, int n4w)
{
    const int which = blockIdx.y;
    const float4* src;
    __half* dst;
    int n4;
    if (which == 0)      { src = x;  dst = g_xh;    n4 = n4x; }
    else if (which == 1) { src = w0; dst = g_wh[0]; n4 = n4w; }
    else if (which == 2) { src = w1; dst = g_wh[1]; n4 = n4w; }
    else if (which == 3) { src = w2; dst = g_wh[2]; n4 = n4w; }
    else                 { src = w3; dst = g_wh[3]; n4 = n4w; }

    for (int i = blockIdx.x * blockDim.x + threadIdx.x; i < n4;
         i += gridDim.x * blockDim.x) {
        float4 v = src[i];
        __half2* hp = reinterpret_cast<__half2*>(dst + 4 * (size_t)i);
        hp[0] = __floats2half2_rn(v.x, v.y);
        hp[1] = __floats2half2_rn(v.z, v.w);
    }
}

// ---------------------------------------------------------------------------
// RoPE cos/sin tables: g_ct[d*2048+s], d in [0,64)
// ---------------------------------------------------------------------------
__global__ void rope_tab_kernel()
{
    int i = blockIdx.x * blockDim.x + threadIdx.x;
    if (i >= 64 * S_LEN) return;
    int d = i >> 11, s = i & 2047;
    float invf = (float)exp2(-(double)d * 0.20762050593045952);  // log2(1e4)/64
    float th = (float)s * invf;
    float c, sn;
    sincosf(th, &sn, &c);
    g_ct[i] = c;
    g_st[i] = sn;
}

// ---------------------------------------------------------------------------
// HMMA GEMM (fp16, single-product): tile 64x256, BK=64, 8 warps (2m x 4n),
// warp 32x64, 2 CTAs/SM.
// Column permutation: warp wn owns head (wn>>1), cols {off..off+31} and
// {off+64..off+95} with off = (wn&1)*32, so register pair (c[.][j], c[.][j+4])
// is exactly the RoPE pair (d, d+64) -> RoPE applied in registers, no smem.
// mode: 0=Q(->g_qhi/g_qlo) 1=K(->g_khi) 2=V(->g_vhi) 3=Wo(A=g_atth,->out)
// QKV launch: mode_in = -1 => mode = blockIdx.z.
// smem/stage: A 8K | B 32K = 40KB, 2 stages = 80KB
// ---------------------------------------------------------------------------
#define GM_BM 64
#define GM_BN 256
#define GM_BK 64
#define GM_NIT (DMODEL / GM_BK)          // 32
#define GM_A 0
#define GM_B 8192
#define GM_STAGE 40960
#define GM_SMEM (2 * GM_STAGE)           // 80KB

__device__ __forceinline__ void gm_load_stage(
    uint32_t t0, int kt, int m0, int n0, int tid,
    const __half* __restrict__ Ah, const __half* __restrict__ Bh)
{
    const int k0 = kt * GM_BK;
    #pragma unroll
    for (int i = 0; i < 2; i++) {
        int lin = tid + i * 256;
        int row = lin >> 3, ch = lin & 7;
        uint32_t soff = (uint32_t)(row * 128 + ((ch ^ (row & 7)) << 4));
        size_t ga = (size_t)(m0 + row) * DMODEL + k0 + ch * 8;
        cp16(t0 + GM_A + soff, Ah + ga);
    }
    #pragma unroll
    for (int i = 0; i < 8; i++) {
        int lin = tid + i * 256;
        int row = lin >> 3, ch = lin & 7;
        uint32_t soff = (uint32_t)(row * 128 + ((ch ^ (row & 7)) << 4));
        size_t gb = (size_t)(n0 + row) * DMODEL + k0 + ch * 8;
        cp16(t0 + GM_B + soff, Bh + gb);
    }
}

__global__ __launch_bounds__(256, 2)
void gemm_hmma(float* __restrict__ Dout, int mode_in)
{
    extern __shared__ char smraw[];
    const uint32_t sbase = (uint32_t)__cvta_generic_to_shared(smraw);
    const int tid  = threadIdx.x;
    const int warp = tid >> 5;
    const int lane = tid & 31;
    const int m0 = blockIdx.y * GM_BM;
    const int n0 = blockIdx.x * GM_BN;
    const int mode = (mode_in < 0) ? (int)blockIdx.z : mode_in;

    const __half* Ah = (mode == 3) ? g_atth : g_xh;
    const __half* Bh = g_wh[mode];

    const int wm = warp & 1;        // 0..1
    const int wn = warp >> 1;       // 0..3
    const int quad = lane >> 3;
    const int lr   = lane & 7;

    int arow[2];
    #pragma unroll
    for (int i = 0; i < 2; i++) arow[i] = wm * 32 + i * 16 + (quad & 1) * 8 + lr;
    const int aqp = quad >> 1;

    // permuted n-tile bases (within 256-col block): head strip + RoPE pairing
    int ncb[4];
    #pragma unroll
    for (int j2 = 0; j2 < 4; j2++)
        ncb[j2] = (wn >> 1) * 128 + (wn & 1) * 32 + (j2 & 1) * 16 + (j2 >> 1) * 64;
    int brow[4];
    #pragma unroll
    for (int j2 = 0; j2 < 4; j2++) brow[j2] = ncb[j2] + (quad >> 1) * 8 + lr;
    const int bqp = quad & 1;

    float c[2][8][4];
    #pragma unroll
    for (int i = 0; i < 2; i++)
        #pragma unroll
        for (int j = 0; j < 8; j++)
            #pragma unroll
            for (int e = 0; e < 4; e++) c[i][j][e] = 0.f;

    gm_load_stage(sbase, 0, m0, n0, tid, Ah, Bh);
    cp_commit();

    #pragma unroll 1
    for (int kt = 0; kt < GM_NIT; kt++) {
        if (kt + 1 < GM_NIT) {
            gm_load_stage(sbase + ((kt + 1) & 1) * GM_STAGE, kt + 1,
                          m0, n0, tid, Ah, Bh);
            cp_commit();
            cp_wait<1>();
        } else {
            cp_wait<0>();
        }
        __syncthreads();

        const uint32_t t0 = sbase + (kt & 1) * GM_STAGE;
        #pragma unroll
        for (int s = 0; s < 4; s++) {
            uint32_t ah[2][4];
            #pragma unroll
            for (int i = 0; i < 2; i++) {
                uint32_t off = (uint32_t)(arow[i] * 128 +
                               (((s * 2 + aqp) ^ (arow[i] & 7)) << 4));
                ldsm4(t0 + GM_A + off, ah[i]);
            }
            uint32_t bh[8][2];
            #pragma unroll
            for (int j2 = 0; j2 < 4; j2++) {
                uint32_t off = (uint32_t)(brow[j2] * 128 +
                               (((s * 2 + bqp) ^ (brow[j2] & 7)) << 4));
                uint32_t t[4];
                ldsm4(t0 + GM_B + off, t);
                bh[2*j2][0] = t[0]; bh[2*j2][1] = t[1];
                bh[2*j2+1][0] = t[2]; bh[2*j2+1][1] = t[3];
            }
            #pragma unroll
            for (int i = 0; i < 2; i++)
                #pragma unroll
                for (int j = 0; j < 8; j++)
                    mma16816(c[i][j], ah[i], bh[j][0], bh[j][1]);
        }
        __syncthreads();
    }

    // ---------------- epilogue ----------------
    // col(j) = n0 + ncb[j>>1] + (j&1)*8 + (lane&3)*2
    // For mode<=1: j in 0..3 gives d in [0,64), j+4 gives d+64 (same head).
    if (mode <= 1) {
        __half* dhi = (mode == 0) ? g_qhi : g_khi;
        const int h = (n0 >> 7) + (wn >> 1);
        #pragma unroll
        for (int i = 0; i < 2; i++) {
            #pragma unroll
            for (int half = 0; half < 2; half++) {
                int r = m0 + wm * 32 + i * 16 + (lane >> 2) + half * 8;
                int bb = r >> 11, ss = r & 2047;
                size_t base = (((size_t)bb * NHEADS + h) * S_LEN + ss) * HDIM;
                #pragma unroll
                for (int j = 0; j < 4; j++) {
                    int d0 = (wn & 1) * 32 + (j >> 1) * 16 + (j & 1) * 8 + (lane & 3) * 2;
                    float lo0 = c[i][j][half * 2],     lo1 = c[i][j][half * 2 + 1];
                    float hi0 = c[i][j + 4][half * 2], hi1 = c[i][j + 4][half * 2 + 1];
                    float c0 = g_ct[d0 * S_LEN + ss],       s0 = g_st[d0 * S_LEN + ss];
                    float c1 = g_ct[(d0 + 1) * S_LEN + ss], s1 = g_st[(d0 + 1) * S_LEN + ss];
                    float v00 = lo0 * c0 - hi0 * s0;   // d0
                    float v10 = hi0 * c0 + lo0 * s0;   // d0+64
                    float v01 = lo1 * c1 - hi1 * s1;   // d0+1
                    float v11 = hi1 * c1 + lo1 * s1;   // d0+65
                    __half2 hlo = __floats2half2_rn(v00, v01);
                    __half2 hhi = __floats2half2_rn(v10, v11);
                    *(__half2*)(dhi + base + d0)      = hlo;
                    *(__half2*)(dhi + base + d0 + 64) = hhi;
                    if (mode == 0) {
                        *(__half2*)(g_qlo + base + d0) = __floats2half2_rn(
                            v00 - __half2float(__low2half(hlo)),
                            v01 - __half2float(__high2half(hlo)));
                        *(__half2*)(g_qlo + base + d0 + 64) = __floats2half2_rn(
                            v10 - __half2float(__low2half(hhi)),
                            v11 - __half2float(__high2half(hhi)));
                    }
                }
            }
        }
    } else {
        #pragma unroll
        for (int i = 0; i < 2; i++) {
            #pragma unroll
            for (int half = 0; half < 2; half++) {
                int r = m0 + wm * 32 + i * 16 + (lane >> 2) + half * 8;
                int bb = r >> 11, ss = r & 2047;
                #pragma unroll
                for (int j = 0; j < 8; j++) {
                    int col = n0 + ncb[j >> 1] + (j & 1) * 8 + (lane & 3) * 2;
                    float2 v2 = make_float2(c[i][j][half * 2], c[i][j][half * 2 + 1]);
                    if (mode == 2) {
                        int h = col >> 7, d = col & 127;
                        size_t base = (((size_t)bb * NHEADS + h) * S_LEN + ss) * HDIM + d;
                        *(__half2*)(g_vhi + base) = __floats2half2_rn(v2.x, v2.y);
                    } else {
                        *(float2*)(Dout + (size_t)r * DMODEL + col) = v2;
                    }
                }
            }
        }
    }
}

// ---------------------------------------------------------------------------
// HMMA flash attention (causal, fp16): CTA = 64 q rows x 64-key tiles,
// 4 warps (128 thr), warp = 16 q rows x all 64 keys, 2 CTAs/SM.
// QK: Q hi+lo (2 products). PV: P hi only.
// smem: Qhi 16K | Qlo 16K | 2 stages x (Khi 16K | Vhi 16K) = 96KB
// ---------------------------------------------------------------------------
#define FA_BM 64
#define FQHI 0
#define FQLO 16384
#define FSTG(s) (32768 + (s) * 32768)
#define FKHI 0
#define FVHI 16384
#define FA_SMEM (32768 + 2 * 32768)   // 96KB

__device__ __forceinline__ uint32_t fswz(int row, int ch) {
    return (uint32_t)(row * 256 + ((ch >> 3) << 7) + (((ch & 7) ^ (row & 7)) << 4));
}

__global__ __launch_bounds__(128, 2)
void flash_hmma()
{
    extern __shared__ char smraw[];
    const uint32_t sb = (uint32_t)__cvta_generic_to_shared(smraw);
    const int tid  = threadIdx.x;
    const int w    = tid >> 5;           // 0..3
    const int lane = tid & 31;
    const int quad = lane >> 3;
    const int lr   = lane & 7;
    const int qt = 31 - blockIdx.x;      // heavy CTAs first, 64-row tiles
    const int bh = blockIdx.y;

    const __half* qhib = g_qhi + (size_t)bh * S_LEN * HDIM;
    const __half* qlob = g_qlo + (size_t)bh * S_LEN * HDIM;
    const __half* khib = g_khi + (size_t)bh * S_LEN * HDIM;
    const __half* vhib = g_vhi + (size_t)bh * S_LEN * HDIM;

    #pragma unroll
    for (int i = 0; i < 8; i++) {
        int lin = tid + i * 128;
        int row = lin >> 4, ch = lin & 15;
        uint32_t so = fswz(row, ch);
        size_t go = (size_t)(qt * FA_BM + row) * HDIM + ch * 8;
        cp16(sb + FQHI + so, qhib + go);
        cp16(sb + FQLO + so, qlob + go);
    }
    cp_commit();

    const int nkt = qt + 1;

    {
        const uint32_t t0 = sb + FSTG(0);
        #pragma unroll
        for (int i = 0; i < 8; i++) {
            int lin = tid + i * 128;
            int row = lin >> 4, ch = lin & 15;
            uint32_t so = fswz(row, ch);
            size_t go = (size_t)row * HDIM + ch * 8;
            cp16(t0 + FKHI + so, khib + go);
            cp16(t0 + FVHI + so, vhib + go);
        }
        cp_commit();
    }

    float o[16][4];
    #pragma unroll
    for (int i = 0; i < 16; i++)
        #pragma unroll
        for (int e = 0; e < 4; e++) o[i][e] = 0.f;
    float mi[2] = {-CUDART_INF_F, -CUDART_INF_F};
    float li[2] = {0.f, 0.f};

    const float scale = 0.08838834764831845f;
    const int ar  = 16 * w + (quad & 1) * 8 + lr;
    const int aqp = quad >> 1;
    const int krb = (quad >> 1) * 8 + lr;
    const int bqp = quad & 1;
    const int vrb = (quad & 1) * 8 + lr;
    const int vqp = quad >> 1;

    #pragma unroll 1
    for (int kt = 0; kt < nkt; kt++) {
        if (kt + 1 < nkt) {
            const uint32_t t0 = sb + FSTG((kt + 1) & 1);
            #pragma unroll
            for (int i = 0; i < 8; i++) {
                int lin = tid + i * 128;
                int row = lin >> 4, ch = lin & 15;
                uint32_t so = fswz(row, ch);
                size_t go = (size_t)((kt + 1) * 64 + row) * HDIM + ch * 8;
                cp16(t0 + FKHI + so, khib + go);
                cp16(t0 + FVHI + so, vhib + go);
            }
            cp_commit();
            cp_wait<1>();
        } else {
            cp_wait<0>();
        }
        __syncthreads();

        const uint32_t stg = sb + FSTG(kt & 1);

        float sc[8][4];
        #pragma unroll
        for (int i = 0; i < 8; i++)
            #pragma unroll
            for (int e = 0; e < 4; e++) sc[i][e] = 0.f;

        #pragma unroll
        for (int s = 0; s < 8; s++) {
            uint32_t qh[4], ql[4];
            uint32_t ao = fswz(ar, s * 2 + aqp);
            ldsm4(sb + FQHI + ao, qh);
            ldsm4(sb + FQLO + ao, ql);
            #pragma unroll
            for (int j2 = 0; j2 < 4; j2++) {
                uint32_t bo = fswz(j2 * 16 + krb, s * 2 + bqp);
                uint32_t th[4];
                ldsm4(stg + FKHI + bo, th);
                mma16816(sc[2*j2],   qh, th[0], th[1]);
                mma16816(sc[2*j2],   ql, th[0], th[1]);
                mma16816(sc[2*j2+1], qh, th[2], th[3]);
                mma16816(sc[2*j2+1], ql, th[2], th[3]);
            }
        }

        const bool needmask = (kt * 64 + 63 > qt * FA_BM + 16 * w);
        const int rbase = qt * FA_BM + 16 * w + (lane >> 2);
        #pragma unroll
        for (int half = 0; half < 2; half++) {
            const int rg = rbase + half * 8;
            float mx = -CUDART_INF_F;
            #pragma unroll
            for (int dj = 0; dj < 8; dj++) {
                #pragma unroll
                for (int e = 0; e < 2; e++) {
                    float v = sc[dj][half * 2 + e] * scale;
                    if (needmask) {
                        int col = kt * 64 + dj * 8 + (lane & 3) * 2 + e;
                        if (col > rg) v = -CUDART_INF_F;
                    }
                    sc[dj][half * 2 + e] = v;
                    mx = fmaxf(mx, v);
                }
            }
            mx = fmaxf(mx, __shfl_xor_sync(0xffffffffu, mx, 1));
            mx = fmaxf(mx, __shfl_xor_sync(0xffffffffu, mx, 2));
            float mnew = fmaxf(mi[half], mx);
            float fct  = __expf(mi[half] - mnew);
            mi[half] = mnew;
            float ssum = 0.f;
            #pragma unroll
            for (int dj = 0; dj < 8; dj++) {
                #pragma unroll
                for (int e = 0; e < 2; e++) {
                    float p = __expf(sc[dj][half * 2 + e] - mnew);
                    sc[dj][half * 2 + e] = p;
                    ssum += p;
                }
            }
            ssum += __shfl_xor_sync(0xffffffffu, ssum, 1);
            ssum += __shfl_xor_sync(0xffffffffu, ssum, 2);
            li[half] = li[half] * fct + ssum;
            #pragma unroll
            for (int dt = 0; dt < 16; dt++) {
                o[dt][half * 2]     *= fct;
                o[dt][half * 2 + 1] *= fct;
            }
        }

        #pragma unroll
        for (int t = 0; t < 4; t++) {
            uint32_t ph[4];
            #pragma unroll
            for (int pair = 0; pair < 2; pair++) {
                const float* sp = sc[2 * t + pair];
                ph[pair * 2 + 0] = pack_h2(sp[0], sp[1]);
                ph[pair * 2 + 1] = pack_h2(sp[2], sp[3]);
            }
            #pragma unroll
            for (int j2 = 0; j2 < 8; j2++) {
                uint32_t vo = fswz(t * 16 + vrb, j2 * 2 + vqp);
                uint32_t vh[4];
                ldsm4t(stg + FVHI + vo, vh);
                mma16816(o[2*j2],   ph, vh[0], vh[1]);
                mma16816(o[2*j2+1], ph, vh[2], vh[3]);
            }
        }
        __syncthreads();
    }

    const int b  = bh >> 4;
    const int hh = bh & 15;
    const float inva = 1.0f / li[0];
    const float invb = 1.0f / li[1];
    const int sa = qt * FA_BM + 16 * w + (lane >> 2);

    #pragma unroll
    for (int dj = 0; dj < 16; dj++) {
        int col = hh * HDIM + dj * 8 + (lane & 3) * 2;
        size_t ia = ((size_t)b * S_LEN + sa) * DMODEL + col;
        size_t ib = ((size_t)b * S_LEN + sa + 8) * DMODEL + col;
        *(__half2*)(g_atth + ia) = __floats2half2_rn(o[dj][0] * inva, o[dj][1] * inva);
        *(__half2*)(g_atth + ib) = __floats2half2_rn(o[dj][2] * invb, o[dj][3] * invb);
    }
}

// ---------------------------------------------------------------------------
// Launch
// ---------------------------------------------------------------------------
extern "C" void kernel_launch(void* const* d_in, const int* in_sizes, int n_in,
                              void* d_out, int out_size)
{
    const float* x  = (const float*)d_in[0];
    const float* Wq = (const float*)d_in[1];
    const float* Wk = (const float*)d_in[2];
    const float* Wv = (const float*)d_in[3];
    const float* Wo = (const float*)d_in[4];
    float* out = (float*)d_out;

    int n4x = MROWS * DMODEL / 4;
    int n4w = DMODEL * DMODEL / 4;
    convert_all_kernel<<<dim3(1024, 5), 256>>>(
        (const float4*)x, (const float4*)Wq, (const float4*)Wk,
        (const float4*)Wv, (const float4*)Wo, n4x, n4w);
    rope_tab_kernel<<<(64 * S_LEN + 255) / 256, 256>>>();

    cudaFuncSetAttribute(gemm_hmma,
                         cudaFuncAttributeMaxDynamicSharedMemorySize, GM_SMEM);

    dim3 gblk(DMODEL / GM_BN, MROWS / GM_BM);       // 8 x 128

    // fused Q/K/V projections (single-product, register RoPE): z = mode
    gemm_hmma<<<dim3(gblk.x, gblk.y, 3), 256, GM_SMEM>>>(nullptr, -1);

    cudaFuncSetAttribute(flash_hmma, cudaFuncAttributeMaxDynamicSharedMemorySize, FA_SMEM);
    flash_hmma<<<dim3(32, BATCH * NHEADS), 128, FA_SMEM>>>();

    gemm_hmma<<<gblk, 256, GM_SMEM>>>(out, 3);   // output projection (1-product)
}

// round 14
// speedup vs baseline: 1.1250x; 1.0657x over previous
#include <cuda_runtime.h>
#include <cuda_fp16.h>
#include <math_constants.h>
#include <cstdint>

// Problem constants
#define S_LEN   2048
#define DMODEL  2048
#define NHEADS  16
#define HDIM    128
#define BATCH   4
#define MROWS   (BATCH * S_LEN)   // 8192

// ---------------------------------------------------------------------------
// Scratch (device globals; no allocation in kernel_launch)
// ---------------------------------------------------------------------------
__device__ __half g_xh[(size_t)MROWS * DMODEL];                // x, fp16
__device__ __half g_wh[4][(size_t)DMODEL * DMODEL];            // weights, fp16
__device__ __half g_qhi[(size_t)BATCH * NHEADS * S_LEN * HDIM];
__device__ __half g_khi[(size_t)BATCH * NHEADS * S_LEN * HDIM];
__device__ __half g_vhi[(size_t)BATCH * NHEADS * S_LEN * HDIM];
__device__ __half g_atth[(size_t)MROWS * DMODEL];              // [B,S,D]
__device__ float g_ct[64 * S_LEN];                              // cos[d][s]
__device__ float g_st[64 * S_LEN];                              // sin[d][s]

// ---------------------------------------------------------------------------
// PTX helpers
// ---------------------------------------------------------------------------
__device__ __forceinline__ void cp16(uint32_t smem_dst, const void* gptr) {
    asm volatile("cp.async.cg.shared.global [%0], [%1], 16;"
                 :: "r"(smem_dst), "l"(__cvta_generic_to_global(gptr)) : "memory");
}
__device__ __forceinline__ void cp_commit() {
    asm volatile("cp.async.commit_group;" ::: "memory");
}
template <int N>
__device__ __forceinline__ void cp_wait() {
    asm volatile("cp.async.wait_group %0;" :: "n"(N) : "memory");
}
__device__ __forceinline__ void ldsm4(uint32_t addr, uint32_t r[4]) {
    asm volatile("ldmatrix.sync.aligned.m8n8.x4.shared.b16 {%0,%1,%2,%3}, [%4];"
                 : "=r"(r[0]), "=r"(r[1]), "=r"(r[2]), "=r"(r[3]) : "r"(addr));
}
__device__ __forceinline__ void ldsm4t(uint32_t addr, uint32_t r[4]) {
    asm volatile("ldmatrix.sync.aligned.m8n8.x4.trans.shared.b16 {%0,%1,%2,%3}, [%4];"
                 : "=r"(r[0]), "=r"(r[1]), "=r"(r[2]), "=r"(r[3]) : "r"(addr));
}
__device__ __forceinline__ void mma16816(float c[4], const uint32_t a[4],
                                         const uint32_t b0, const uint32_t b1) {
    asm volatile(
        "mma.sync.aligned.m16n8k16.row.col.f32.f16.f16.f32 "
        "{%0,%1,%2,%3}, {%4,%5,%6,%7}, {%8,%9}, {%0,%1,%2,%3};"
        : "+f"(c[0]), "+f"(c[1]), "+f"(c[2]), "+f"(c[3])
        : "r"(a[0]), "r"(a[1]), "r"(a[2]), "r"(a[3]), "r"(b0), "r"(b1));
}
__device__ __forceinline__ uint32_t pack_h2(float x, float y) {
    __half2 t = __floats2half2_rn(x, y);
    return *reinterpret_cast<uint32_t*>(&t);
}

// ---------------------------------------------------------------------------
// Fused fp32 -> fp16 converts: y = 0 -> x, y = 1..4 -> Wq/Wk/Wv/Wo
// ---------------------------------------------------------------------------
__global__ void convert_all_kernel(const float4* __restrict__ x,
                                   const float4* __restrict__ w0,
                                   const float4* __restrict__ w1,
                                   const float4* __restrict__ w2,
                                   const float4* __restrict__ w3,
                                   int n4x, int n4w)
{
    const int which = blockIdx.y;
    const float4* src;
    __half* dst;
    int n4;
    if (which == 0)      { src = x;  dst = g_xh;    n4 = n4x; }
    else if (which == 1) { src = w0; dst = g_wh[0]; n4 = n4w; }
    else if (which == 2) { src = w1; dst = g_wh[1]; n4 = n4w; }
    else if (which == 3) { src = w2; dst = g_wh[2]; n4 = n4w; }
    else                 { src = w3; dst = g_wh[3]; n4 = n4w; }

    for (int i = blockIdx.x * blockDim.x + threadIdx.x; i < n4;
         i += gridDim.x * blockDim.x) {
        float4 v = src[i];
        __half2* hp = reinterpret_cast<__half2*>(dst + 4 * (size_t)i);
        hp[0] = __floats2half2_rn(v.x, v.y);
        hp[1] = __floats2half2_rn(v.z, v.w);
    }
}

// ---------------------------------------------------------------------------
// RoPE cos/sin tables: g_ct[d*2048+s], d in [0,64)
// ---------------------------------------------------------------------------
__global__ void rope_tab_kernel()
{
    int i = blockIdx.x * blockDim.x + threadIdx.x;
    if (i >= 64 * S_LEN) return;
    int d = i >> 11, s = i & 2047;
    float invf = (float)exp2(-(double)d * 0.20762050593045952);  // log2(1e4)/64
    float th = (float)s * invf;
    float c, sn;
    sincosf(th, &sn, &c);
    g_ct[i] = c;
    g_st[i] = sn;
}

// ---------------------------------------------------------------------------
// HMMA GEMM (fp16, single-product): tile 64x256, BK=64, 8 warps (2m x 4n),
// warp 32x64, 2 CTAs/SM.  Register RoPE via warp-column permutation:
// warp wn owns head (wn>>1), cols {off..off+31} u {off+64..off+95},
// off=(wn&1)*32, so (c[.][j], c[.][j+4]) is the RoPE pair (d, d+64).
// mode: 0=Q(->g_qhi) 1=K(->g_khi) 2=V(->g_vhi) 3=Wo(A=g_atth,->out)
// QKV launch: mode_in = -1 => mode = blockIdx.z.
// smem/stage: A 8K | B 32K = 40KB, 2 stages = 80KB
// ---------------------------------------------------------------------------
#define GM_BM 64
#define GM_BN 256
#define GM_BK 64
#define GM_NIT (DMODEL / GM_BK)          // 32
#define GM_A 0
#define GM_B 8192
#define GM_STAGE 40960
#define GM_SMEM (2 * GM_STAGE)           // 80KB

__device__ __forceinline__ void gm_load_stage(
    uint32_t t0, int kt, int m0, int n0, int tid,
    const __half* __restrict__ Ah, const __half* __restrict__ Bh)
{
    const int k0 = kt * GM_BK;
    #pragma unroll
    for (int i = 0; i < 2; i++) {
        int lin = tid + i * 256;
        int row = lin >> 3, ch = lin & 7;
        uint32_t soff = (uint32_t)(row * 128 + ((ch ^ (row & 7)) << 4));
        size_t ga = (size_t)(m0 + row) * DMODEL + k0 + ch * 8;
        cp16(t0 + GM_A + soff, Ah + ga);
    }
    #pragma unroll
    for (int i = 0; i < 8; i++) {
        int lin = tid + i * 256;
        int row = lin >> 3, ch = lin & 7;
        uint32_t soff = (uint32_t)(row * 128 + ((ch ^ (row & 7)) << 4));
        size_t gb = (size_t)(n0 + row) * DMODEL + k0 + ch * 8;
        cp16(t0 + GM_B + soff, Bh + gb);
    }
}

__global__ __launch_bounds__(256, 2)
void gemm_hmma(float* __restrict__ Dout, int mode_in)
{
    extern __shared__ char smraw[];
    const uint32_t sbase = (uint32_t)__cvta_generic_to_shared(smraw);
    const int tid  = threadIdx.x;
    const int warp = tid >> 5;
    const int lane = tid & 31;
    const int m0 = blockIdx.y * GM_BM;
    const int n0 = blockIdx.x * GM_BN;
    const int mode = (mode_in < 0) ? (int)blockIdx.z : mode_in;

    const __half* Ah = (mode == 3) ? g_atth : g_xh;
    const __half* Bh = g_wh[mode];

    const int wm = warp & 1;        // 0..1
    const int wn = warp >> 1;       // 0..3
    const int quad = lane >> 3;
    const int lr   = lane & 7;

    int arow[2];
    #pragma unroll
    for (int i = 0; i < 2; i++) arow[i] = wm * 32 + i * 16 + (quad & 1) * 8 + lr;
    const int aqp = quad >> 1;

    // permuted n-tile bases (within 256-col block): head strip + RoPE pairing
    int ncb[4];
    #pragma unroll
    for (int j2 = 0; j2 < 4; j2++)
        ncb[j2] = (wn >> 1) * 128 + (wn & 1) * 32 + (j2 & 1) * 16 + (j2 >> 1) * 64;
    int brow[4];
    #pragma unroll
    for (int j2 = 0; j2 < 4; j2++) brow[j2] = ncb[j2] + (quad >> 1) * 8 + lr;
    const int bqp = quad & 1;

    float c[2][8][4];
    #pragma unroll
    for (int i = 0; i < 2; i++)
        #pragma unroll
        for (int j = 0; j < 8; j++)
            #pragma unroll
            for (int e = 0; e < 4; e++) c[i][j][e] = 0.f;

    gm_load_stage(sbase, 0, m0, n0, tid, Ah, Bh);
    cp_commit();

    #pragma unroll 1
    for (int kt = 0; kt < GM_NIT; kt++) {
        if (kt + 1 < GM_NIT) {
            gm_load_stage(sbase + ((kt + 1) & 1) * GM_STAGE, kt + 1,
                          m0, n0, tid, Ah, Bh);
            cp_commit();
            cp_wait<1>();
        } else {
            cp_wait<0>();
        }
        __syncthreads();

        const uint32_t t0 = sbase + (kt & 1) * GM_STAGE;
        #pragma unroll
        for (int s = 0; s < 4; s++) {
            uint32_t ah[2][4];
            #pragma unroll
            for (int i = 0; i < 2; i++) {
                uint32_t off = (uint32_t)(arow[i] * 128 +
                               (((s * 2 + aqp) ^ (arow[i] & 7)) << 4));
                ldsm4(t0 + GM_A + off, ah[i]);
            }
            uint32_t bh[8][2];
            #pragma unroll
            for (int j2 = 0; j2 < 4; j2++) {
                uint32_t off = (uint32_t)(brow[j2] * 128 +
                               (((s * 2 + bqp) ^ (brow[j2] & 7)) << 4));
                uint32_t t[4];
                ldsm4(t0 + GM_B + off, t);
                bh[2*j2][0] = t[0]; bh[2*j2][1] = t[1];
                bh[2*j2+1][0] = t[2]; bh[2*j2+1][1] = t[3];
            }
            #pragma unroll
            for (int i = 0; i < 2; i++)
                #pragma unroll
                for (int j = 0; j < 8; j++)
                    mma16816(c[i][j], ah[i], bh[j][0], bh[j][1]);
        }
        __syncthreads();
    }

    // ---------------- epilogue ----------------
    if (mode <= 1) {
        __half* dhi = (mode == 0) ? g_qhi : g_khi;
        const int h = (n0 >> 7) + (wn >> 1);
        #pragma unroll
        for (int i = 0; i < 2; i++) {
            #pragma unroll
            for (int half = 0; half < 2; half++) {
                int r = m0 + wm * 32 + i * 16 + (lane >> 2) + half * 8;
                int bb = r >> 11, ss = r & 2047;
                size_t base = (((size_t)bb * NHEADS + h) * S_LEN + ss) * HDIM;
                #pragma unroll
                for (int j = 0; j < 4; j++) {
                    int d0 = (wn & 1) * 32 + (j >> 1) * 16 + (j & 1) * 8 + (lane & 3) * 2;
                    float lo0 = c[i][j][half * 2],     lo1 = c[i][j][half * 2 + 1];
                    float hi0 = c[i][j + 4][half * 2], hi1 = c[i][j + 4][half * 2 + 1];
                    float c0 = g_ct[d0 * S_LEN + ss],       s0 = g_st[d0 * S_LEN + ss];
                    float c1 = g_ct[(d0 + 1) * S_LEN + ss], s1 = g_st[(d0 + 1) * S_LEN + ss];
                    float v00 = lo0 * c0 - hi0 * s0;   // d0
                    float v10 = hi0 * c0 + lo0 * s0;   // d0+64
                    float v01 = lo1 * c1 - hi1 * s1;   // d0+1
                    float v11 = hi1 * c1 + lo1 * s1;   // d0+65
                    *(__half2*)(dhi + base + d0)      = __floats2half2_rn(v00, v01);
                    *(__half2*)(dhi + base + d0 + 64) = __floats2half2_rn(v10, v11);
                }
            }
        }
    } else {
        #pragma unroll
        for (int i = 0; i < 2; i++) {
            #pragma unroll
            for (int half = 0; half < 2; half++) {
                int r = m0 + wm * 32 + i * 16 + (lane >> 2) + half * 8;
                int bb = r >> 11, ss = r & 2047;
                #pragma unroll
                for (int j = 0; j < 8; j++) {
                    int col = n0 + ncb[j >> 1] + (j & 1) * 8 + (lane & 3) * 2;
                    float2 v2 = make_float2(c[i][j][half * 2], c[i][j][half * 2 + 1]);
                    if (mode == 2) {
                        int h = col >> 7, d = col & 127;
                        size_t base = (((size_t)bb * NHEADS + h) * S_LEN + ss) * HDIM + d;
                        *(__half2*)(g_vhi + base) = __floats2half2_rn(v2.x, v2.y);
                    } else {
                        *(float2*)(Dout + (size_t)r * DMODEL + col) = v2;
                    }
                }
            }
        }
    }
}

// ---------------------------------------------------------------------------
// HMMA flash attention (causal, fp16): CTA = 64 q rows x 64-key tiles,
// 4 warps (128 thr), warp = 16 q rows x all 64 keys, 2 CTAs/SM.
// QK: pure fp16 (1 product). PV: P hi only (1 product).
// smem: Qhi 16K | 2 stages x (Khi 16K | Vhi 16K) = 80KB
// ---------------------------------------------------------------------------
#define FA_BM 64
#define FQHI 0
#define FSTG(s) (16384 + (s) * 32768)
#define FKHI 0
#define FVHI 16384
#define FA_SMEM (16384 + 2 * 32768)   // 80KB

__device__ __forceinline__ uint32_t fswz(int row, int ch) {
    return (uint32_t)(row * 256 + ((ch >> 3) << 7) + (((ch & 7) ^ (row & 7)) << 4));
}

__global__ __launch_bounds__(128, 2)
void flash_hmma()
{
    extern __shared__ char smraw[];
    const uint32_t sb = (uint32_t)__cvta_generic_to_shared(smraw);
    const int tid  = threadIdx.x;
    const int w    = tid >> 5;           // 0..3
    const int lane = tid & 31;
    const int quad = lane >> 3;
    const int lr   = lane & 7;
    const int qt = 31 - blockIdx.x;      // heavy CTAs first, 64-row tiles
    const int bh = blockIdx.y;

    const __half* qhib = g_qhi + (size_t)bh * S_LEN * HDIM;
    const __half* khib = g_khi + (size_t)bh * S_LEN * HDIM;
    const __half* vhib = g_vhi + (size_t)bh * S_LEN * HDIM;

    // Q tile: 64 rows x 16 chunks, 128 threads x 8 iters
    #pragma unroll
    for (int i = 0; i < 8; i++) {
        int lin = tid + i * 128;
        int row = lin >> 4, ch = lin & 15;
        uint32_t so = fswz(row, ch);
        size_t go = (size_t)(qt * FA_BM + row) * HDIM + ch * 8;
        cp16(sb + FQHI + so, qhib + go);
    }
    cp_commit();

    const int nkt = qt + 1;

    {
        const uint32_t t0 = sb + FSTG(0);
        #pragma unroll
        for (int i = 0; i < 8; i++) {
            int lin = tid + i * 128;
            int row = lin >> 4, ch = lin & 15;
            uint32_t so = fswz(row, ch);
            size_t go = (size_t)row * HDIM + ch * 8;
            cp16(t0 + FKHI + so, khib + go);
            cp16(t0 + FVHI + so, vhib + go);
        }
        cp_commit();
    }

    float o[16][4];
    #pragma unroll
    for (int i = 0; i < 16; i++)
        #pragma unroll
        for (int e = 0; e < 4; e++) o[i][e] = 0.f;
    float mi[2] = {-CUDART_INF_F, -CUDART_INF_F};
    float li[2] = {0.f, 0.f};

    const float scale = 0.08838834764831845f;
    const int ar  = 16 * w + (quad & 1) * 8 + lr;
    const int aqp = quad >> 1;
    const int krb = (quad >> 1) * 8 + lr;
    const int bqp = quad & 1;
    const int vrb = (quad & 1) * 8 + lr;
    const int vqp = quad >> 1;

    #pragma unroll 1
    for (int kt = 0; kt < nkt; kt++) {
        if (kt + 1 < nkt) {
            const uint32_t t0 = sb + FSTG((kt + 1) & 1);
            #pragma unroll
            for (int i = 0; i < 8; i++) {
                int lin = tid + i * 128;
                int row = lin >> 4, ch = lin & 15;
                uint32_t so = fswz(row, ch);
                size_t go = (size_t)((kt + 1) * 64 + row) * HDIM + ch * 8;
                cp16(t0 + FKHI + so, khib + go);
                cp16(t0 + FVHI + so, vhib + go);
            }
            cp_commit();
            cp_wait<1>();
        } else {
            cp_wait<0>();
        }
        __syncthreads();

        const uint32_t stg = sb + FSTG(kt & 1);

        float sc[8][4];
        #pragma unroll
        for (int i = 0; i < 8; i++)
            #pragma unroll
            for (int e = 0; e < 4; e++) sc[i][e] = 0.f;

        #pragma unroll
        for (int s = 0; s < 8; s++) {
            uint32_t qh[4];
            uint32_t ao = fswz(ar, s * 2 + aqp);
            ldsm4(sb + FQHI + ao, qh);
            #pragma unroll
            for (int j2 = 0; j2 < 4; j2++) {
                uint32_t bo = fswz(j2 * 16 + krb, s * 2 + bqp);
                uint32_t th[4];
                ldsm4(stg + FKHI + bo, th);
                mma16816(sc[2*j2],   qh, th[0], th[1]);
                mma16816(sc[2*j2+1], qh, th[2], th[3]);
            }
        }

        const bool needmask = (kt * 64 + 63 > qt * FA_BM + 16 * w);
        const int rbase = qt * FA_BM + 16 * w + (lane >> 2);
        #pragma unroll
        for (int half = 0; half < 2; half++) {
            const int rg = rbase + half * 8;
            float mx = -CUDART_INF_F;
            #pragma unroll
            for (int dj = 0; dj < 8; dj++) {
                #pragma unroll
                for (int e = 0; e < 2; e++) {
                    float v = sc[dj][half * 2 + e] * scale;
                    if (needmask) {
                        int col = kt * 64 + dj * 8 + (lane & 3) * 2 + e;
                        if (col > rg) v = -CUDART_INF_F;
                    }
                    sc[dj][half * 2 + e] = v;
                    mx = fmaxf(mx, v);
                }
            }
            mx = fmaxf(mx, __shfl_xor_sync(0xffffffffu, mx, 1));
            mx = fmaxf(mx, __shfl_xor_sync(0xffffffffu, mx, 2));
            float mnew = fmaxf(mi[half], mx);
            float fct  = __expf(mi[half] - mnew);
            mi[half] = mnew;
            float ssum = 0.f;
            #pragma unroll
            for (int dj = 0; dj < 8; dj++) {
                #pragma unroll
                for (int e = 0; e < 2; e++) {
                    float p = __expf(sc[dj][half * 2 + e] - mnew);
                    sc[dj][half * 2 + e] = p;
                    ssum += p;
                }
            }
            ssum += __shfl_xor_sync(0xffffffffu, ssum, 1);
            ssum += __shfl_xor_sync(0xffffffffu, ssum, 2);
            li[half] = li[half] * fct + ssum;
            #pragma unroll
            for (int dt = 0; dt < 16; dt++) {
                o[dt][half * 2]     *= fct;
                o[dt][half * 2 + 1] *= fct;
            }
        }

        #pragma unroll
        for (int t = 0; t < 4; t++) {
            uint32_t ph[4];
            #pragma unroll
            for (int pair = 0; pair < 2; pair++) {
                const float* sp = sc[2 * t + pair];
                ph[pair * 2 + 0] = pack_h2(sp[0], sp[1]);
                ph[pair * 2 + 1] = pack_h2(sp[2], sp[3]);
            }
            #pragma unroll
            for (int j2 = 0; j2 < 8; j2++) {
                uint32_t vo = fswz(t * 16 + vrb, j2 * 2 + vqp);
                uint32_t vh[4];
                ldsm4t(stg + FVHI + vo, vh);
                mma16816(o[2*j2],   ph, vh[0], vh[1]);
                mma16816(o[2*j2+1], ph, vh[2], vh[3]);
            }
        }
        __syncthreads();
    }

    const int b  = bh >> 4;
    const int hh = bh & 15;
    const float inva = 1.0f / li[0];
    const float invb = 1.0f / li[1];
    const int sa = qt * FA_BM + 16 * w + (lane >> 2);

    #pragma unroll
    for (int dj = 0; dj < 16; dj++) {
        int col = hh * HDIM + dj * 8 + (lane & 3) * 2;
        size_t ia = ((size_t)b * S_LEN + sa) * DMODEL + col;
        size_t ib = ((size_t)b * S_LEN + sa + 8) * DMODEL + col;
        *(__half2*)(g_atth + ia) = __floats2half2_rn(o[dj][0] * inva, o[dj][1] * inva);
        *(__half2*)(g_atth + ib) = __floats2half2_rn(o[dj][2] * invb, o[dj][3] * invb);
    }
}

// ---------------------------------------------------------------------------
// Launch
// ---------------------------------------------------------------------------
extern "C" void kernel_launch(void* const* d_in, const int* in_sizes, int n_in,
                              void* d_out, int out_size)
{
    const float* x  = (const float*)d_in[0];
    const float* Wq = (const float*)d_in[1];
    const float* Wk = (const float*)d_in[2];
    const float* Wv = (const float*)d_in[3];
    const float* Wo = (const float*)d_in[4];
    float* out = (float*)d_out;

    int n4x = MROWS * DMODEL / 4;
    int n4w = DMODEL * DMODEL / 4;
    convert_all_kernel<<<dim3(1024, 5), 256>>>(
        (const float4*)x, (const float4*)Wq, (const float4*)Wk,
        (const float4*)Wv, (const float4*)Wo, n4x, n4w);
    rope_tab_kernel<<<(64 * S_LEN + 255) / 256, 256>>>();

    cudaFuncSetAttribute(gemm_hmma,
                         cudaFuncAttributeMaxDynamicSharedMemorySize, GM_SMEM);

    dim3 gblk(DMODEL / GM_BN, MROWS / GM_BM);       // 8 x 128

    // fused Q/K/V projections (single-product, register RoPE): z = mode
    gemm_hmma<<<dim3(gblk.x, gblk.y, 3), 256, GM_SMEM>>>(nullptr, -1);

    cudaFuncSetAttribute(flash_hmma, cudaFuncAttributeMaxDynamicSharedMemorySize, FA_SMEM);
    flash_hmma<<<dim3(32, BATCH * NHEADS), 128, FA_SMEM>>>();

    gemm_hmma<<<gblk, 256, GM_SMEM>>>(out, 3);   // output projection (1-product)
}